// round 17
// baseline (speedup 1.0000x reference)
#include <cuda_runtime.h>
#include <cuda_fp16.h>
#include <math.h>
#include <cstdint>

#define NHEAD  16
#define DMODEL 1024
#define DHEAD  64
#define BATCH  2
#define SEQ    2048
#define MROWS  (BATCH*SEQ)   // 4096
#define MASKN  ((size_t)BATCH*SEQ*SEQ)
#define MASKW  (MASKN/32)    // packed words
#define KC     1024          // single-term fp16 GEMM K
#define ACTN   ((size_t)MROWS*DMODEL)
#define PACKN  ((size_t)32*SEQ*64)   // packed q/k/v: 64 fp16 per row

// Scratch (device globals; no allocation in kernel_launch)
__device__ float g_y  [MROWS*DMODEL];
__device__ uint32_t g_maskb[MASKW];              // bit-packed mask, 1MB
__device__ int g_fmt;
__device__ __half g_acat3[(size_t)3*MROWS*KC];   // 25.2MB (q|k|v activations fp16)
__device__ __half g_wcat3[(size_t)3*DMODEL*KC];  // 6.3MB  (w_q|w_k|w_v transposed)
__device__ __half g_wcat [(size_t)DMODEL*KC];    // 2.1MB  (w_o transposed)
__device__ __half g_acat [(size_t)MROWS*KC];     // 8.4MB  (attn out fp16)
__device__ __half g_qkvc[(size_t)3*PACKN];       // qc|kc|vc, 25.2MB

// ======================= mma.sync + cp.async helpers =======================
__device__ __forceinline__ void mma16816(float* c, const uint32_t* a, const uint32_t* b) {
    asm volatile("mma.sync.aligned.m16n8k16.row.col.f32.f16.f16.f32 "
        "{%0,%1,%2,%3}, {%4,%5,%6,%7}, {%8,%9}, {%0,%1,%2,%3};"
        : "+f"(c[0]), "+f"(c[1]), "+f"(c[2]), "+f"(c[3])
        : "r"(a[0]), "r"(a[1]), "r"(a[2]), "r"(a[3]), "r"(b[0]), "r"(b[1]));
}
__device__ __forceinline__ void ldsm4(uint32_t* r, uint32_t addr) {
    asm volatile("ldmatrix.sync.aligned.m8n8.x4.shared.b16 {%0,%1,%2,%3}, [%4];"
        : "=r"(r[0]), "=r"(r[1]), "=r"(r[2]), "=r"(r[3]) : "r"(addr));
}
__device__ __forceinline__ void ldsm4t(uint32_t* r, uint32_t addr) {
    asm volatile("ldmatrix.sync.aligned.m8n8.x4.trans.shared.b16 {%0,%1,%2,%3}, [%4];"
        : "=r"(r[0]), "=r"(r[1]), "=r"(r[2]), "=r"(r[3]) : "r"(addr));
}
__device__ __forceinline__ uint32_t smem_u32(const void* p) {
    uint32_t a;
    asm("{ .reg .u64 t; cvta.to.shared.u64 t, %1; cvt.u32.u64 %0, t; }" : "=r"(a) : "l"(p));
    return a;
}
__device__ __forceinline__ void cp16(uint32_t dst, const void* src) {
    asm volatile("cp.async.cg.shared.global [%0], [%1], 16;" :: "r"(dst), "l"(src));
}
#define CP_COMMIT() asm volatile("cp.async.commit_group;" ::: "memory")
#define CP_WAIT2()  asm volatile("cp.async.wait_group 2;" ::: "memory")
#define CP_WAIT1()  asm volatile("cp.async.wait_group 1;" ::: "memory")
#define CP_WAIT0()  asm volatile("cp.async.wait_group 0;" ::: "memory")

// single fp16 pack of a float pair
__device__ __forceinline__ uint32_t pack1(float x, float y) {
    __half2 p = __halves2half2(__float2half(x), __float2half(y));
    return *(uint32_t*)&p;
}

// ======================= mask dtype probe + bit-pack =======================
__global__ void probe_mask(const unsigned int* __restrict__ m) {
    __shared__ int s_i32, s_f32;
    if (threadIdx.x == 0) { s_i32 = 1; s_f32 = 1; }
    __syncthreads();
    int bad_i = 0, bad_f = 0;
    for (int i = threadIdx.x; i < (1 << 16); i += blockDim.x) {
        unsigned int w = m[i];
        if (w != 0u && w != 1u) bad_i = 1;
        if (w != 0u && w != 0x3F800000u) bad_f = 1;
    }
    if (bad_i) atomicAnd(&s_i32, 0);
    if (bad_f) atomicAnd(&s_f32, 0);
    __syncthreads();
    if (threadIdx.x == 0) g_fmt = s_i32 ? 1 : (s_f32 ? 2 : 0);
}
// Each thread packs 32 mask values into one uint32 (bit k = value!=0).
__global__ void pack_mask(const void* __restrict__ src) {
    size_t w = (size_t)blockIdx.x * blockDim.x + threadIdx.x;
    if (w >= MASKW) return;
    int fmt = g_fmt;
    uint32_t bits = 0;
    if (fmt == 0) {
        const uint4* p = (const uint4*)src + w * 2;
        uint4 a = p[0], b = p[1];
        uint32_t vals[8] = {a.x, a.y, a.z, a.w, b.x, b.y, b.z, b.w};
#pragma unroll
        for (int j = 0; j < 8; j++) {
            uint32_t v = vals[j];
            uint32_t nib = (v & 1u) | ((v >> 7) & 2u) | ((v >> 14) & 4u) | ((v >> 21) & 8u);
            bits |= nib << (j * 4);
        }
    } else if (fmt == 1) {
        const int* p = (const int*)src + w * 32;
#pragma unroll
        for (int j = 0; j < 32; j++) bits |= (uint32_t)(p[j] != 0) << j;
    } else {
        const float* p = (const float*)src + w * 32;
#pragma unroll
        for (int j = 0; j < 32; j++) bits |= (uint32_t)(p[j] != 0.f) << j;
    }
    g_maskb[w] = bits;
}

// ======================= fp16 conversions ==================================
__global__ void split_act3(const float* __restrict__ q, const float* __restrict__ k,
                           const float* __restrict__ v, __half* __restrict__ out) {
    const size_t N4 = ACTN / 4;
    size_t i = (size_t)blockIdx.x * blockDim.x + threadIdx.x;
    if (i >= 3 * N4) return;
    int z = (int)(i / N4);
    size_t j = i % N4;
    const float* src = (z == 0) ? q : (z == 1) ? k : v;
    float4 val = ((const float4*)src)[j];
    uint2 o;
    o.x = pack1(val.x, val.y);
    o.y = pack1(val.z, val.w);
    ((uint2*)(out + (size_t)z * ACTN))[j] = o;
}

// All four weights in one launch. z<3: headed [h,d,e] -> wcat3. z==3: w_o flat.
__global__ void __launch_bounds__(256) split_w_all(
    const float* __restrict__ wq, const float* __restrict__ wk,
    const float* __restrict__ wv, const float* __restrict__ wo,
    __half* __restrict__ out3, __half* __restrict__ outo)
{
    __shared__ float t[64][65];
    const int bx = blockIdx.x, by = blockIdx.y, z = blockIdx.z;
    const int tid = threadIdx.x;

    if (z < 3) {
        const int dt = bx, h = by;
        const float* src = (z == 0) ? wq : (z == 1) ? wk : wv;
#pragma unroll
        for (int i = 0; i < 16; i++) {
            int idx = tid + i * 256;
            int dr = idx >> 6, e = idx & 63;
            t[dr][e] = src[((size_t)h * DMODEL + dt * 64 + dr) * DHEAD + e];
        }
        __syncthreads();
#pragma unroll
        for (int i = 0; i < 16; i++) {
            int idx = tid + i * 256;
            int e = idx >> 6, dr = idx & 63;
            int n = h * DHEAD + e, d = dt * 64 + dr;
            out3[(size_t)z * DMODEL * KC + (size_t)n * KC + d] = __float2half(t[dr][e]);
        }
    } else {
        const int dt = bx, nt = by;
#pragma unroll
        for (int i = 0; i < 16; i++) {
            int idx = tid + i * 256;
            int dr = idx >> 6, nr = idx & 63;
            t[dr][nr] = wo[(size_t)(dt * 64 + dr) * DMODEL + nt * 64 + nr];
        }
        __syncthreads();
#pragma unroll
        for (int i = 0; i < 16; i++) {
            int idx = tid + i * 256;
            int nr = idx >> 6, dr = idx & 63;
            int n = nt * 64 + nr, d = dt * 64 + dr;
            outo[(size_t)n * KC + d] = __float2half(t[dr][nr]);
        }
    }
}

// ======================= mma.sync GEMM machinery ===========================
// 3-stage cp.async pipeline (2 stages in flight).
#define GBK     64
#define GNITER  (KC / GBK)                   // 16
#define TILE_B  (128 * 72 * 2)               // 18432 bytes per A or B tile
#define BUF_B   (2 * TILE_B)                 // 36864 per stage (A+B)
#define GEMM_SMEM (3 * BUF_B)                // 110592 (x2 CTAs = 221KB, fits)

__device__ __forceinline__ void gemm_load_stage(
    uint32_t dst, const __half* Ag, const __half* Bg, int tid)
{
#pragma unroll
    for (int i = 0; i < 4; i++) {
        int idx = tid + i * 256;
        int r = idx >> 3, ch = idx & 7;
        cp16(dst + r * 144 + ch * 16,          Ag + (size_t)r * KC + ch * 8);
        cp16(dst + TILE_B + r * 144 + ch * 16, Bg + (size_t)r * KC + ch * 8);
    }
    CP_COMMIT();
}

__device__ __forceinline__ void gemm_mainloop(
    const __half* Ag0, const __half* Bg0,
    uint32_t smb, const char* smc, int tid, float acc[4][4][4])
{
    const int wid = tid >> 5, lid = tid & 31;
    const int wm = wid >> 2, wn = wid & 3;
    const int lrow = lid & 7, quad = lid >> 3;
    const uint32_t aoff = (uint32_t)(((quad & 1) * 8 + lrow) * 144 + (quad >> 1) * 16)
                        + (uint32_t)(wm * 64) * 144;
    const uint32_t boff = (uint32_t)(((quad >> 1) * 8 + lrow) * 144 + (quad & 1) * 16)
                        + (uint32_t)(wn * 32) * 144 + TILE_B;

    // prologue: stages 0 and 1
    gemm_load_stage(smb,          Ag0,       Bg0,       tid);
    gemm_load_stage(smb + BUF_B,  Ag0 + GBK, Bg0 + GBK, tid);

    int buf = 0;
    for (int it = 0; it < GNITER; it++) {
        if (it + 2 < GNITER) {
            int nb = buf + 2; if (nb >= 3) nb -= 3;
            gemm_load_stage(smb + nb * BUF_B,
                            Ag0 + (it + 2) * GBK, Bg0 + (it + 2) * GBK, tid);
            CP_WAIT2();
        } else if (it + 1 < GNITER) {
            CP_WAIT1();
        } else {
            CP_WAIT0();
        }
        __syncthreads();

        const uint32_t bb = smb + buf * BUF_B;
#pragma unroll
        for (int ks = 0; ks < 4; ks++) {
            uint32_t a[4][4], bq[2][4];
#pragma unroll
            for (int mt = 0; mt < 4; mt++)
                ldsm4(a[mt], bb + aoff + (uint32_t)(mt * 16) * 144 + ks * 32);
#pragma unroll
            for (int p = 0; p < 2; p++)
                ldsm4(bq[p], bb + boff + (uint32_t)(p * 16) * 144 + ks * 32);
#pragma unroll
            for (int mt = 0; mt < 4; mt++)
#pragma unroll
                for (int p = 0; p < 2; p++) {
                    mma16816(acc[mt][2 * p],     a[mt], &bq[p][0]);
                    mma16816(acc[mt][2 * p + 1], a[mt], &bq[p][2]);
                }
        }
        __syncthreads();
        if (++buf == 3) buf = 0;
    }
}

// Projection GEMM: grid.z selects q/k/v; packed [hb][row][64 fp16] output.
__global__ void __launch_bounds__(256, 2) gemm_proj(
    const __half* __restrict__ A3, const __half* __restrict__ B3,
    __half* __restrict__ Cp3)
{
    extern __shared__ char smc[];
    const uint32_t smb = smem_u32(smc);
    const int tid = threadIdx.x;
    const int wid = tid >> 5, lid = tid & 31;
    const int wm = wid >> 2, wn = wid & 3;
    const int g = lid >> 2, tg = lid & 3;
    const int m0 = blockIdx.y * 128, n0 = blockIdx.x * 128;
    const int z = blockIdx.z;

    const __half* Ag0 = A3 + (size_t)z * MROWS * KC + (size_t)m0 * KC;
    const __half* Bg0 = B3 + (size_t)z * DMODEL * KC + (size_t)n0 * KC;
    __half* Cp = Cp3 + (size_t)z * PACKN;

    float acc[4][4][4];
#pragma unroll
    for (int mt = 0; mt < 4; mt++)
#pragma unroll
        for (int nt = 0; nt < 4; nt++)
#pragma unroll
            for (int r = 0; r < 4; r++) acc[mt][nt][r] = 0.f;

    gemm_mainloop(Ag0, Bg0, smb, smc, tid, acc);

#pragma unroll
    for (int mt = 0; mt < 4; mt++) {
        int m = m0 + wm * 64 + mt * 16 + g;
#pragma unroll
        for (int nt = 0; nt < 4; nt++) {
            int n = n0 + wn * 32 + nt * 8 + 2 * tg;
            int h = n >> 6, e = n & 63;
#pragma unroll
            for (int half_ = 0; half_ < 2; half_++) {
                int mm = m + half_ * 8;
                int b = mm >> 11, qq = mm & 2047;
                int hb = (h << 1) + b;
                uint32_t hv = pack1(acc[mt][nt][2 * half_], acc[mt][nt][2 * half_ + 1]);
                __half* o = Cp + ((size_t)hb * SEQ + qq) * 64;
                *(uint32_t*)(o + e) = hv;
            }
        }
    }
}

// Output projection GEMM: fp32 C + bias + residual.
__global__ void __launch_bounds__(256, 2) gemm_out(
    const __half* __restrict__ A, const __half* __restrict__ Bt,
    float* __restrict__ Cf, const float* __restrict__ bias,
    const float* __restrict__ residual)
{
    extern __shared__ char smc[];
    const uint32_t smb = smem_u32(smc);
    const int tid = threadIdx.x;
    const int wid = tid >> 5, lid = tid & 31;
    const int wm = wid >> 2, wn = wid & 3;
    const int g = lid >> 2, tg = lid & 3;
    const int m0 = blockIdx.y * 128, n0 = blockIdx.x * 128;

    const __half* Ag0 = A  + (size_t)m0 * KC;
    const __half* Bg0 = Bt + (size_t)n0 * KC;

    float acc[4][4][4];
#pragma unroll
    for (int mt = 0; mt < 4; mt++)
#pragma unroll
        for (int nt = 0; nt < 4; nt++)
#pragma unroll
            for (int r = 0; r < 4; r++) acc[mt][nt][r] = 0.f;

    gemm_mainloop(Ag0, Bg0, smb, smc, tid, acc);

#pragma unroll
    for (int mt = 0; mt < 4; mt++) {
        int m = m0 + wm * 64 + mt * 16 + g;
#pragma unroll
        for (int nt = 0; nt < 4; nt++) {
            int n = n0 + wn * 32 + nt * 8 + 2 * tg;
            float2 v0 = make_float2(acc[mt][nt][0], acc[mt][nt][1]);
            float2 v1 = make_float2(acc[mt][nt][2], acc[mt][nt][3]);
            float2 bv = *(const float2*)(bias + n);
            float2 r0 = *(const float2*)(residual + (size_t)m * DMODEL + n);
            float2 r1 = *(const float2*)(residual + (size_t)(m + 8) * DMODEL + n);
            v0.x += bv.x + r0.x; v0.y += bv.y + r0.y;
            v1.x += bv.x + r1.x; v1.y += bv.y + r1.y;
            *(float2*)(Cf + (size_t)m * DMODEL + n)       = v0;
            *(float2*)(Cf + (size_t)(m + 8) * DMODEL + n) = v1;
        }
    }
}

// ======================= flash attention via mma.sync (fp16) ===============
// 128-key pipeline stages, 2 CTAs/SM, bit-packed mask (uint32 = 32 keys).
#define AQ_OFF  0
#define AQ_TB   18432                 // 128 rows x 144B
#define KV_TB2  18432                 // 128 rows x 144B per stage
#define AK_OFF  AQ_TB
#define AV_OFF  (AQ_TB + 2*KV_TB2)
#define ATT_SMEM (AQ_TB + 4*KV_TB2)   // 92160
#define NSTAGE  (SEQ / 128)           // 16
#define MWPR    (SEQ / 32)            // 64 mask words per q row

__global__ void __launch_bounds__(256, 2) attn_mma(
    const __half* __restrict__ Qc, const __half* __restrict__ Kc,
    const __half* __restrict__ Vc, const uint32_t* __restrict__ maskb,
    __half* __restrict__ acat)
{
    extern __shared__ char smc[];
    const uint32_t smb = smem_u32(smc);
    const int tid = threadIdx.x;
    const int wid = tid >> 5, lid = tid & 31;
    const int g = lid >> 2, tg = lid & 3;
    const int qb = blockIdx.x, hb = blockIdx.y;
    const int h = hb >> 1, b = hb & 1;
    const int q0 = qb * 128;
    const int qrow = wid * 16;

    const int lrow = lid & 7, quad = lid >> 3;
    const uint32_t aoff = (uint32_t)(((quad & 1) * 8 + lrow) * 144 + (quad >> 1) * 16)
                        + (uint32_t)qrow * 144;
    const uint32_t boff = (uint32_t)(((quad >> 1) * 8 + lrow) * 144 + (quad & 1) * 16);
    const uint32_t voff = (uint32_t)(((quad & 1) * 8 + lrow) * 144 + (quad >> 1) * 16);

    const uint32_t* mb0 = maskb + ((size_t)b * SEQ + q0 + qrow + g) * MWPR;
    const uint32_t* mb1 = mb0 + 8 * MWPR;

    // ---- load Q tile (persistent) + first K/V stage (128 keys)
    {
        const __half* Qg = Qc + ((size_t)hb * SEQ + q0) * 64;
#pragma unroll
        for (int i = 0; i < 4; i++) {
            int idx = tid + i * 256;
            int r = idx >> 3, ch = idx & 7;
            cp16(smb + AQ_OFF + r * 144 + ch * 16, Qg + (size_t)r * 64 + ch * 8);
        }
        const __half* Kg = Kc + ((size_t)hb * SEQ) * 64;
        const __half* Vg = Vc + ((size_t)hb * SEQ) * 64;
#pragma unroll
        for (int i = 0; i < 4; i++) {
            int idx = tid + i * 256;
            int r = idx >> 3, ch = idx & 7;
            cp16(smb + AK_OFF + r * 144 + ch * 16, Kg + (size_t)r * 64 + ch * 8);
            cp16(smb + AV_OFF + r * 144 + ch * 16, Vg + (size_t)r * 64 + ch * 8);
        }
        CP_COMMIT();
    }

    float o_acc[8][4];
#pragma unroll
    for (int nt = 0; nt < 8; nt++)
#pragma unroll
        for (int r = 0; r < 4; r++) o_acc[nt][r] = 0.f;
    float m0 = -1e30f, m1 = -1e30f, l0 = 0.f, l1 = 0.f;

    int buf = 0;

    for (int st = 0; st < NSTAGE; st++) {
        if (st + 1 < NSTAGE) {
            const __half* Kg = Kc + ((size_t)hb * SEQ + (st + 1) * 128) * 64;
            const __half* Vg = Vc + ((size_t)hb * SEQ + (st + 1) * 128) * 64;
            const uint32_t kb_ = smb + AK_OFF + (buf ^ 1) * KV_TB2;
            const uint32_t vb_ = smb + AV_OFF + (buf ^ 1) * KV_TB2;
#pragma unroll
            for (int i = 0; i < 4; i++) {
                int idx = tid + i * 256;
                int r = idx >> 3, ch = idx & 7;
                cp16(kb_ + r * 144 + ch * 16, Kg + (size_t)r * 64 + ch * 8);
                cp16(vb_ + r * 144 + ch * 16, Vg + (size_t)r * 64 + ch * 8);
            }
            CP_COMMIT();
            CP_WAIT1();
        } else {
            CP_WAIT0();
        }
        __syncthreads();

        const uint32_t Qb = smb + AQ_OFF;

#pragma unroll
        for (int sub = 0; sub < 2; sub++) {
            const uint32_t Kb = smb + AK_OFF + buf * KV_TB2 + (uint32_t)(sub * 64) * 144;
            const uint32_t Vb = smb + AV_OFF + buf * KV_TB2 + (uint32_t)(sub * 64) * 144;
            const int kt = st * 2 + sub;

            const uint2 mw0 = *(const uint2*)(mb0 + kt * 2);
            const uint2 mw1 = *(const uint2*)(mb1 + kt * 2);

            // ---- S = Q K^T (single-term fp16)
            float s[8][4];
#pragma unroll
            for (int nt = 0; nt < 8; nt++)
#pragma unroll
                for (int r = 0; r < 4; r++) s[nt][r] = 0.f;

#pragma unroll
            for (int kb = 0; kb < 4; kb++) {
                uint32_t bq[4][4];
#pragma unroll
                for (int p = 0; p < 4; p++)
                    ldsm4(bq[p], Kb + boff + (uint32_t)(p * 16) * 144 + kb * 32);
                uint32_t a[4];
                ldsm4(a, Qb + aoff + kb * 32);
#pragma unroll
                for (int p = 0; p < 4; p++) {
                    mma16816(s[2 * p],     a, &bq[p][0]);
                    mma16816(s[2 * p + 1], a, &bq[p][2]);
                }
            }

            // ---- scale + mask (bit tests)
#pragma unroll
            for (int nt = 0; nt < 8; nt++) {
                const uint32_t w0 = (nt < 4) ? mw0.x : mw0.y;
                const uint32_t w1 = (nt < 4) ? mw1.x : mw1.y;
                const int bi = (nt & 3) * 8 + 2 * tg;
                s[nt][0] = ((w0 >> bi) & 1u)       ? -1e30f : s[nt][0] * 0.125f;
                s[nt][1] = ((w0 >> (bi + 1)) & 1u) ? -1e30f : s[nt][1] * 0.125f;
                s[nt][2] = ((w1 >> bi) & 1u)       ? -1e30f : s[nt][2] * 0.125f;
                s[nt][3] = ((w1 >> (bi + 1)) & 1u) ? -1e30f : s[nt][3] * 0.125f;
            }

            // ---- online softmax
            float mt0 = -1e30f, mt1 = -1e30f;
#pragma unroll
            for (int nt = 0; nt < 8; nt++) {
                mt0 = fmaxf(mt0, fmaxf(s[nt][0], s[nt][1]));
                mt1 = fmaxf(mt1, fmaxf(s[nt][2], s[nt][3]));
            }
            mt0 = fmaxf(mt0, __shfl_xor_sync(0xffffffffu, mt0, 1));
            mt0 = fmaxf(mt0, __shfl_xor_sync(0xffffffffu, mt0, 2));
            mt1 = fmaxf(mt1, __shfl_xor_sync(0xffffffffu, mt1, 1));
            mt1 = fmaxf(mt1, __shfl_xor_sync(0xffffffffu, mt1, 2));
            const float mn0 = fmaxf(m0, mt0), mn1 = fmaxf(m1, mt1);
            const float f0 = __expf(m0 - mn0), f1 = __expf(m1 - mn1);

            float ls0 = 0.f, ls1 = 0.f;
#pragma unroll
            for (int nt = 0; nt < 8; nt++) {
                s[nt][0] = __expf(s[nt][0] - mn0);
                s[nt][1] = __expf(s[nt][1] - mn0);
                s[nt][2] = __expf(s[nt][2] - mn1);
                s[nt][3] = __expf(s[nt][3] - mn1);
                ls0 += s[nt][0] + s[nt][1];
                ls1 += s[nt][2] + s[nt][3];
            }
            ls0 += __shfl_xor_sync(0xffffffffu, ls0, 1);
            ls0 += __shfl_xor_sync(0xffffffffu, ls0, 2);
            ls1 += __shfl_xor_sync(0xffffffffu, ls1, 1);
            ls1 += __shfl_xor_sync(0xffffffffu, ls1, 2);
            l0 = l0 * f0 + ls0; l1 = l1 * f1 + ls1;
            m0 = mn0; m1 = mn1;

#pragma unroll
            for (int nt = 0; nt < 8; nt++) {
                o_acc[nt][0] *= f0; o_acc[nt][1] *= f0;
                o_acc[nt][2] *= f1; o_acc[nt][3] *= f1;
            }

            // ---- P fragments (single fp16, A-frag layout)
            uint32_t pf[4][4];
#pragma unroll
            for (int ks = 0; ks < 4; ks++) {
                pf[ks][0] = pack1(s[2*ks][0],   s[2*ks][1]);
                pf[ks][1] = pack1(s[2*ks][2],   s[2*ks][3]);
                pf[ks][2] = pack1(s[2*ks+1][0], s[2*ks+1][1]);
                pf[ks][3] = pack1(s[2*ks+1][2], s[2*ks+1][3]);
            }

            // ---- O += P V (single-term fp16) via trans-ldmatrix
#pragma unroll
            for (int kb = 0; kb < 4; kb++) {
                const uint32_t krow = Vb + voff + (uint32_t)(kb * 16) * 144;
                uint32_t bt[4][4];
#pragma unroll
                for (int nt = 0; nt < 4; nt++)
                    ldsm4t(bt[nt], krow + nt * 32);
#pragma unroll
                for (int nt = 0; nt < 4; nt++) {
                    mma16816(o_acc[2 * nt],     pf[kb], &bt[nt][0]);
                    mma16816(o_acc[2 * nt + 1], pf[kb], &bt[nt][2]);
                }
            }
        }
        __syncthreads();
        buf ^= 1;
    }

    // ---- epilogue: normalize, single fp16, write acat [row][1024]
    const float inv0 = 1.f / l0, inv1 = 1.f / l1;
    const int row0 = b * SEQ + q0 + qrow + g;
    const int row1 = row0 + 8;
    __half* p0 = acat + (size_t)row0 * KC;
    __half* p1 = acat + (size_t)row1 * KC;
#pragma unroll
    for (int nt = 0; nt < 8; nt++) {
        const int d = h * 64 + nt * 8 + 2 * tg;
        *(uint32_t*)(p0 + d) = pack1(o_acc[nt][0] * inv0, o_acc[nt][1] * inv0);
        *(uint32_t*)(p1 + d) = pack1(o_acc[nt][2] * inv1, o_acc[nt][3] * inv1);
    }
}

// ======================= LayerNorm (torch semantics, float4) ===============
__global__ void __launch_bounds__(256) ln_kernel(
    const float* __restrict__ y, const float* __restrict__ gamma,
    const float* __restrict__ beta, float* __restrict__ out)
{
    __shared__ float sh_s[8], sh_ss[8];
    const int row = blockIdx.x;
    const float4* x4 = (const float4*)(y + (size_t)row * DMODEL);
    const float4 xv = x4[threadIdx.x];

    float s  = xv.x + xv.y + xv.z + xv.w;
    float ss = xv.x * xv.x + xv.y * xv.y + xv.z * xv.z + xv.w * xv.w;
#pragma unroll
    for (int o = 16; o > 0; o >>= 1) {
        s  += __shfl_xor_sync(0xffffffffu, s,  o);
        ss += __shfl_xor_sync(0xffffffffu, ss, o);
    }
    int warp = threadIdx.x >> 5, lane = threadIdx.x & 31;
    if (lane == 0) { sh_s[warp] = s; sh_ss[warp] = ss; }
    __syncthreads();
    if (threadIdx.x < 32) {
        s  = (lane < 8) ? sh_s[lane]  : 0.f;
        ss = (lane < 8) ? sh_ss[lane] : 0.f;
#pragma unroll
        for (int o = 4; o > 0; o >>= 1) {
            s  += __shfl_xor_sync(0xffffffffu, s,  o);
            ss += __shfl_xor_sync(0xffffffffu, ss, o);
        }
        if (lane == 0) { sh_s[0] = s; sh_ss[0] = ss; }
    }
    __syncthreads();
    float mean = sh_s[0] * (1.f / DMODEL);
    float var  = (sh_ss[0] - (float)DMODEL * mean * mean) * (1.f / (DMODEL - 1));
    var = fmaxf(var, 0.f);
    float inv = 1.f / (sqrtf(var) + 1e-3f);

    const float4 gv = ((const float4*)gamma)[threadIdx.x];
    const float4 bv = ((const float4*)beta)[threadIdx.x];
    float4 ov;
    ov.x = (xv.x - mean) * inv * gv.x + bv.x;
    ov.y = (xv.y - mean) * inv * gv.y + bv.y;
    ov.z = (xv.z - mean) * inv * gv.z + bv.z;
    ov.w = (xv.w - mean) * inv * gv.w + bv.w;
    ((float4*)(out + (size_t)row * DMODEL))[threadIdx.x] = ov;
}

// ===========================================================================
extern "C" void kernel_launch(void* const* d_in, const int* in_sizes, int n_in,
                              void* d_out, int out_size)
{
    const float* v     = (const float*)d_in[0];
    const float* k     = (const float*)d_in[1];
    const float* q     = (const float*)d_in[2];
    const void*  mask  = (const void*)d_in[3];
    const float* w_q   = (const float*)d_in[4];
    const float* w_k   = (const float*)d_in[5];
    const float* w_v   = (const float*)d_in[6];
    const float* w_o   = (const float*)d_in[7];
    const float* b_o   = (const float*)d_in[8];
    const float* gamma = (const float*)d_in[9];
    const float* beta  = (const float*)d_in[10];
    float*       out   = (float*)d_out;

    float* y;
    uint32_t* maskb;
    __half *acat3, *wcat3, *wcat, *acat, *qkvc;
    cudaGetSymbolAddress((void**)&y,     g_y);
    cudaGetSymbolAddress((void**)&maskb, g_maskb);
    cudaGetSymbolAddress((void**)&acat3, g_acat3);
    cudaGetSymbolAddress((void**)&wcat3, g_wcat3);
    cudaGetSymbolAddress((void**)&wcat,  g_wcat);
    cudaGetSymbolAddress((void**)&acat,  g_acat);
    cudaGetSymbolAddress((void**)&qkvc,  g_qkvc);

    cudaFuncSetAttribute(gemm_proj, cudaFuncAttributeMaxDynamicSharedMemorySize, GEMM_SMEM);
    cudaFuncSetAttribute(gemm_out,  cudaFuncAttributeMaxDynamicSharedMemorySize, GEMM_SMEM);
    cudaFuncSetAttribute(attn_mma,  cudaFuncAttributeMaxDynamicSharedMemorySize, ATT_SMEM);

    __half* qc = qkvc;
    __half* kc = qkvc + PACKN;
    __half* vc = qkvc + 2 * PACKN;

    // Mask -> bit-packed
    probe_mask<<<1, 1024>>>((const unsigned int*)mask);
    pack_mask<<<(int)((MASKW + 255) / 256), 256>>>(mask);

    // Conversions
    split_act3<<<(int)((3 * (ACTN / 4) + 255) / 256), 256>>>(q, k, v, acat3);
    dim3 wgrid(DMODEL / 64, 16, 4);
    split_w_all<<<wgrid, 256>>>(w_q, w_k, w_v, w_o, wcat3, wcat);

    // All three projections (1-term fp16) -> packed qc/kc/vc
    dim3 pgrid(DMODEL / 128, MROWS / 128, 3);    // (8, 32, 3)
    gemm_proj<<<pgrid, 256, GEMM_SMEM>>>(acat3, wcat3, qkvc);

    // Flash attention (single-term fp16 S and PV, bit-packed mask)
    dim3 agrid(SEQ / 128, NHEAD * BATCH);
    attn_mma<<<agrid, 256, ATT_SMEM>>>(qc, kc, vc, maskb, acat);

    // Output projection (1-term fp16) + bias + residual(k)
    dim3 ggrid(DMODEL / 128, MROWS / 128);
    gemm_out<<<ggrid, 256, GEMM_SMEM>>>(acat, wcat, y, b_o, k);

    // LayerNorm
    ln_kernel<<<MROWS, 256>>>(y, gamma, beta, out);
}